// round 7
// baseline (speedup 1.0000x reference)
#include <cuda_runtime.h>
#include <math.h>

#define N_NODES 4096
#define WORDS   64
#define HID     256
#define VOCAB   50257
#define NCLASS  4
#define N_LEAF  2048

// ---------------- device scratch (static: no allocations allowed) ----------------
__device__ float    g_ET[(size_t)VOCAB * HID];   // E transposed: [VOCAB][HID]
__device__ float    g_X [N_NODES * HID];         // gathered embeddings
__device__ float    g_WX[N_NODES * 3 * HID];     // [n][ z | r | h ]
__device__ float    g_UZP[HID * HID];            // packed U_z (eighth-split layout, see k_packU)
__device__ float    g_URP[HID * HID];
__device__ float    g_UHP[HID * HID];
__device__ float    g_H [N_NODES * HID];         // node hidden states
__device__ float    g_PR[N_NODES * HID];         // published ph*r slices (intra-node exchange)
__device__ unsigned g_flag[N_NODES];             // node-done counters (8 = complete)
__device__ unsigned g_exc[N_NODES];              // intra-node exchange counters (8 = complete)
__device__ float    g_red[32 * HID];             // leaf-max partials

// ---------------- helpers ----------------
__device__ __forceinline__ unsigned ld_acq(const unsigned* p) {
    unsigned v;
    asm volatile("ld.acquire.gpu.global.u32 %0, [%1];" : "=r"(v) : "l"(p) : "memory");
    return v;
}
__device__ __forceinline__ void red_add_release(unsigned* p) {
    asm volatile("red.add.release.gpu.global.u32 [%0], %1;" :: "l"(p), "r"(1u) : "memory");
}
__device__ __forceinline__ unsigned long long pk2(float a, float b) {
    unsigned long long r;
    asm("mov.b64 %0, {%1, %2};" : "=l"(r) : "f"(a), "f"(b));
    return r;
}
__device__ __forceinline__ unsigned long long ffma2(unsigned long long a, unsigned long long b,
                                                    unsigned long long c) {
    unsigned long long d;
    asm("fma.rn.f32x2 %0, %1, %2, %3;" : "=l"(d) : "l"(a), "l"(b), "l"(c));
    return d;
}
__device__ __forceinline__ float hsum2(unsigned long long a) {
    float lo, hi;
    asm("mov.b64 {%0, %1}, %2;" : "=f"(lo), "=f"(hi) : "l"(a));
    return lo + hi;
}

// ---------------- kernels ----------------

__global__ void k_zero_flags() {
    int i = blockIdx.x * blockDim.x + threadIdx.x;
    if (i < N_NODES) {
        g_flag[i] = (i == 0) ? 8u : 0u;   // node 0 produced by gather
        g_exc[i] = 0u;
    }
}

// Tiled transpose E (HID, VOCAB) -> g_ET (VOCAB, HID)
__global__ void k_transposeE(const float* __restrict__ E) {
    __shared__ float tile[32][33];
    int v0 = blockIdx.x * 32;
    int h0 = blockIdx.y * 32;
    int x = threadIdx.x, y = threadIdx.y;  // block (32,8)
    #pragma unroll
    for (int j = 0; j < 32; j += 8) {
        int v = v0 + x;
        if (v < VOCAB) tile[y + j][x] = E[(size_t)(h0 + y + j) * VOCAB + v];
    }
    __syncthreads();
    #pragma unroll
    for (int j = 0; j < 32; j += 8) {
        int v = v0 + y + j;
        if (v < VOCAB) g_ET[(size_t)v * HID + h0 + x] = tile[x][y + j];
    }
}

// Pack U for the eighth-split GRU:
// float4 index ((q*8+ks)*8+kq)*32 + o  holds  U[t=q*32+o][k=ks*32+kq*4 .. +3]
__global__ void k_packU(const float* __restrict__ Uz,
                        const float* __restrict__ Ur,
                        const float* __restrict__ Uh) {
    int gid = blockIdx.x * blockDim.x + threadIdx.x;
    if (gid >= 3 * HID * HID) return;
    int m   = gid >> 16;
    int idx = gid & 65535;
    int t = idx >> 8;
    int k = idx & 255;
    int q = t >> 5, o = t & 31;
    int ks = k >> 5, kk = k & 31, kq = kk >> 2, j = kk & 3;
    int dst = (((q * 8 + ks) * 8 + kq) * 32 + o) * 4 + j;
    const float* src = (m == 0) ? Uz : (m == 1) ? Ur : Uh;
    float*       d   = (m == 0) ? g_UZP : (m == 1) ? g_URP : g_UHP;
    d[dst] = src[t * HID + k];
}

// X[n][t] = sum_w ET[tree[n][w]][t];  also seeds h[0] = X[0]
__global__ __launch_bounds__(HID) void k_gather(const int* __restrict__ tree) {
    int n = blockIdx.x;
    int t = threadIdx.x;
    __shared__ int w[WORDS];
    if (t < WORDS) w[t] = tree[n * WORDS + t];
    __syncthreads();
    float acc = 0.f;
    #pragma unroll 8
    for (int i = 0; i < WORDS; i++)
        acc += g_ET[(size_t)w[i] * HID + t];
    g_X[n * HID + t] = acc;
    if (n == 0) g_H[t] = acc;
}

// WX = X @ [Wz;Wr;Wh]^T  : (4096 x 768), K = 256.  64x64 tile, 4x4 micro.
#define GTM 64
#define GTN 64
#define GTK 32
__global__ __launch_bounds__(256) void k_gemm(const float* __restrict__ Wz,
                                              const float* __restrict__ Wr,
                                              const float* __restrict__ Wh) {
    __shared__ float As[GTK][65];
    __shared__ float Bs[GTK][65];
    int mB = blockIdx.x;
    int jB = blockIdx.y;
    int tid = threadIdx.x;
    int tm = tid >> 4;
    int tn = tid & 15;

    int gate = (jB * GTN) >> 8;
    const float* W = (gate == 0) ? Wz : (gate == 1) ? Wr : Wh;
    int jrow0 = jB * GTN - gate * HID;

    int lrow = tid >> 3;
    int lq   = tid & 7;

    float acc[4][4];
    #pragma unroll
    for (int i = 0; i < 4; i++)
        #pragma unroll
        for (int j = 0; j < 4; j++) acc[i][j] = 0.f;

    for (int kt = 0; kt < HID; kt += GTK) {
        #pragma unroll
        for (int p = 0; p < 2; p++) {
            int r = lrow + p * 32;
            float4 a = *reinterpret_cast<const float4*>(&g_X[(mB * GTM + r) * HID + kt + lq * 4]);
            As[lq * 4 + 0][r] = a.x; As[lq * 4 + 1][r] = a.y;
            As[lq * 4 + 2][r] = a.z; As[lq * 4 + 3][r] = a.w;
            float4 b = *reinterpret_cast<const float4*>(&W[(jrow0 + r) * HID + kt + lq * 4]);
            Bs[lq * 4 + 0][r] = b.x; Bs[lq * 4 + 1][r] = b.y;
            Bs[lq * 4 + 2][r] = b.z; Bs[lq * 4 + 3][r] = b.w;
        }
        __syncthreads();
        #pragma unroll
        for (int kk = 0; kk < GTK; kk++) {
            float a0 = As[kk][tm * 4 + 0], a1 = As[kk][tm * 4 + 1];
            float a2 = As[kk][tm * 4 + 2], a3 = As[kk][tm * 4 + 3];
            float b0 = Bs[kk][tn * 4 + 0], b1 = Bs[kk][tn * 4 + 1];
            float b2 = Bs[kk][tn * 4 + 2], b3 = Bs[kk][tn * 4 + 3];
            acc[0][0] = fmaf(a0, b0, acc[0][0]); acc[0][1] = fmaf(a0, b1, acc[0][1]);
            acc[0][2] = fmaf(a0, b2, acc[0][2]); acc[0][3] = fmaf(a0, b3, acc[0][3]);
            acc[1][0] = fmaf(a1, b0, acc[1][0]); acc[1][1] = fmaf(a1, b1, acc[1][1]);
            acc[1][2] = fmaf(a1, b2, acc[1][2]); acc[1][3] = fmaf(a1, b3, acc[1][3]);
            acc[2][0] = fmaf(a2, b0, acc[2][0]); acc[2][1] = fmaf(a2, b1, acc[2][1]);
            acc[2][2] = fmaf(a2, b2, acc[2][2]); acc[2][3] = fmaf(a2, b3, acc[2][3]);
            acc[3][0] = fmaf(a3, b0, acc[3][0]); acc[3][1] = fmaf(a3, b1, acc[3][1]);
            acc[3][2] = fmaf(a3, b2, acc[3][2]); acc[3][3] = fmaf(a3, b3, acc[3][3]);
        }
        __syncthreads();
    }
    #pragma unroll
    for (int i = 0; i < 4; i++) {
        int m = mB * GTM + tm * 4 + i;
        #pragma unroll
        for (int j = 0; j < 4; j++)
            g_WX[m * (3 * HID) + jB * GTN + tn * 4 + j] = acc[i][j];
    }
}

// GRU wavefront, 8 CTAs per node (32 outputs each).
// All parent-independent data (U_z, U_r slices -> registers; U_h slice -> SMEM;
// WX rows, biases) is prefetched BEFORE the parent spin, so the critical path
// carries almost no load bandwidth — only sync latency + FMA + one 32KB LDS pass.
__global__ __launch_bounds__(256, 2) void k_gru(const int* __restrict__ edge,
                                                const float* __restrict__ bz,
                                                const float* __restrict__ br,
                                                const float* __restrict__ bh) {
    int grp  = blockIdx.x >> 3;
    int q    = blockIdx.x & 7;
    int node = grp + 1;
    int tid  = threadIdx.x;
    int o    = tid & 31;
    int ks   = tid >> 5;   // 0..7 (K slice)

    __shared__ float  sph[HID];
    __shared__ float  spr[HID];
    __shared__ float  saz[8][32];
    __shared__ float  sar[8][32];
    __shared__ float  sch[8][32];
    __shared__ float  sz[32];
    __shared__ float4 uhs[8 * 256];   // 32KB U_h slice (manual spill)

    const float4* UZ4 = reinterpret_cast<const float4*>(g_UZP);
    const float4* UR4 = reinterpret_cast<const float4*>(g_URP);
    const float4* UH4 = reinterpret_cast<const float4*>(g_UHP);

    int p = edge[node * 2];

    // ---- parent-independent prefetch (off the critical path) ----
    int B = ((q * 8 + ks) * 8) * 32 + o;   // float4 tile base; +kq*32 per k step
    float4 uz[8], ur[8];
    #pragma unroll
    for (int i = 0; i < 8; i++) {
        uz[i] = UZ4[B + i * 32];
        ur[i] = UR4[B + i * 32];
        uhs[i * 256 + tid] = UH4[B + i * 32];
    }

    float wzx = 0.f, wrx = 0.f, whx = 0.f, bzv = 0.f, brv = 0.f, bhv = 0.f;
    if (tid < 32) {
        int t = q * 32 + o;
        wzx = g_WX[node * (3 * HID) + t];
        wrx = g_WX[node * (3 * HID) + HID + t];
        whx = g_WX[node * (3 * HID) + 2 * HID + t];
        bzv = bz[t]; brv = br[t]; bhv = bh[t];
    }

    // ---- wait for parent (acquire) ----
    while (ld_acq(&g_flag[p]) < 8u) { }
    sph[tid] = __ldcg(&g_H[p * HID + tid]);
    __syncthreads();

    // ---- phase 1: z, r partial dots from registers (K slice ks: 32 values) ----
    const unsigned long long* sph64 = reinterpret_cast<const unsigned long long*>(sph);
    unsigned long long az0 = 0ull, az1 = 0ull, ar0 = 0ull, ar1 = 0ull;
    int pb = ks * 16;   // ull base for this K slice
    #pragma unroll
    for (int kq = 0; kq < 8; kq++) {
        unsigned long long p0 = sph64[pb + kq * 2];
        unsigned long long p1 = sph64[pb + kq * 2 + 1];
        az0 = ffma2(pk2(uz[kq].x, uz[kq].y), p0, az0);
        az1 = ffma2(pk2(uz[kq].z, uz[kq].w), p1, az1);
        ar0 = ffma2(pk2(ur[kq].x, ur[kq].y), p0, ar0);
        ar1 = ffma2(pk2(ur[kq].z, ur[kq].w), p1, ar1);
    }
    saz[ks][o] = hsum2(az0) + hsum2(az1);
    sar[ks][o] = hsum2(ar0) + hsum2(ar1);
    __syncthreads();

    if (tid < 32) {
        int t = q * 32 + o;
        float az = wzx + bzv, ar = wrx + brv;
        #pragma unroll
        for (int j = 0; j < 8; j++) { az += saz[j][o]; ar += sar[j][o]; }
        float z = 1.f / (1.f + __expf(-az));
        float r = 1.f / (1.f + __expf(-ar));
        float prv = sph[t] * r;
        sz[o] = z;
        g_PR[node * HID + t] = prv;
        __threadfence();
    }
    __syncthreads();
    if (tid == 0) red_add_release(&g_exc[node]);

    // ---- intra-node exchange: gather full pr vector ----
    while (ld_acq(&g_exc[node]) < 8u) { }
    spr[tid] = __ldcg(&g_PR[node * HID + tid]);
    __syncthreads();

    // ---- phase 2: h partial dots with SMEM-prefetched U_h ----
    const unsigned long long* spr64 = reinterpret_cast<const unsigned long long*>(spr);
    unsigned long long ah0 = 0ull, ah1 = 0ull;
    #pragma unroll
    for (int kq = 0; kq < 8; kq++) {
        float4 uh = uhs[kq * 256 + tid];
        unsigned long long p0 = spr64[pb + kq * 2];
        unsigned long long p1 = spr64[pb + kq * 2 + 1];
        ah0 = ffma2(pk2(uh.x, uh.y), p0, ah0);
        ah1 = ffma2(pk2(uh.z, uh.w), p1, ah1);
    }
    sch[ks][o] = hsum2(ah0) + hsum2(ah1);
    __syncthreads();

    if (tid < 32) {
        int t = q * 32 + o;
        float ahv = whx + bhv;
        #pragma unroll
        for (int j = 0; j < 8; j++) ahv += sch[j][o];
        float c = tanhf(ahv);
        float z = sz[o];
        float h = z * sph[t] + (1.f - z) * c;
        g_H[node * HID + t] = h;
        __threadfence();
    }
    __syncthreads();
    if (tid == 0) red_add_release(&g_flag[node]);
}

// 32 partial leaf-max blocks
__global__ __launch_bounds__(HID) void k_leafmax(const int* __restrict__ leaf) {
    int b = blockIdx.x;
    int t = threadIdx.x;
    float m = -INFINITY;
    for (int i = b; i < N_LEAF; i += 32) {
        int n = leaf[i];
        m = fmaxf(m, g_H[n * HID + t]);
    }
    g_red[b * HID + t] = m;
}

__global__ __launch_bounds__(HID) void k_final(const float* __restrict__ Wout,
                                               const float* __restrict__ bout,
                                               const float* __restrict__ y,
                                               float* __restrict__ out, int out_size) {
    __shared__ float f[HID];
    __shared__ float red[HID];
    __shared__ float logits[NCLASS];
    int t = threadIdx.x;
    float m = g_red[t];
    #pragma unroll
    for (int b = 1; b < 32; b++) m = fmaxf(m, g_red[b * HID + t]);
    f[t] = m;
    __syncthreads();
    for (int c = 0; c < NCLASS; c++) {
        red[t] = Wout[c * HID + t] * f[t];
        __syncthreads();
        for (int s = HID / 2; s > 0; s >>= 1) {
            if (t < s) red[t] += red[t + s];
            __syncthreads();
        }
        if (t == 0) logits[c] = red[0] + bout[c];
        __syncthreads();
    }
    if (t == 0) {
        float mx = logits[0];
        for (int c = 1; c < NCLASS; c++) mx = fmaxf(mx, logits[c]);
        float e[NCLASS], s = 0.f;
        for (int c = 0; c < NCLASS; c++) { e[c] = expf(logits[c] - mx); s += e[c]; }
        float loss = 0.f;
        for (int c = 0; c < NCLASS; c++) {
            float pred = e[c] / s;
            float d = y[c] - pred;
            loss += d * d;
            if (c < out_size) out[c] = pred;
        }
        if (out_size > NCLASS) out[NCLASS] = loss;
    }
    for (int i = NCLASS + 1 + t; i < out_size; i += HID) out[i] = 0.f;
}

// ---------------- launch ----------------
extern "C" void kernel_launch(void* const* d_in, const int* in_sizes, int n_in,
                              void* d_out, int out_size) {
    const int*   tree  = (const int*)  d_in[0];
    const int*   edge  = (const int*)  d_in[1];
    const int*   leaf  = (const int*)  d_in[2];
    const float* y     = (const float*)d_in[3];
    const float* E     = (const float*)d_in[4];
    const float* W_z   = (const float*)d_in[5];
    const float* U_z   = (const float*)d_in[6];
    const float* b_z   = (const float*)d_in[7];
    const float* W_r   = (const float*)d_in[8];
    const float* U_r   = (const float*)d_in[9];
    const float* b_r   = (const float*)d_in[10];
    const float* W_h   = (const float*)d_in[11];
    const float* U_h   = (const float*)d_in[12];
    const float* b_h   = (const float*)d_in[13];
    const float* W_out = (const float*)d_in[14];
    const float* b_out = (const float*)d_in[15];
    float* out = (float*)d_out;

    k_zero_flags<<<(N_NODES + 255) / 256, 256>>>();

    dim3 tb(32, 8);
    dim3 tg((VOCAB + 31) / 32, HID / 32);
    k_transposeE<<<tg, tb>>>(E);

    k_packU<<<(3 * HID * HID + 255) / 256, 256>>>(U_z, U_r, U_h);

    k_gather<<<N_NODES, HID>>>(tree);

    dim3 gg(N_NODES / GTM, (3 * HID) / GTN);
    k_gemm<<<gg, 256>>>(W_z, W_r, W_h);

    k_gru<<<8 * (N_NODES - 1), 256>>>(edge, b_z, b_r, b_h);

    k_leafmax<<<32, HID>>>(leaf);
    k_final<<<1, HID>>>(W_out, b_out, y, out, out_size);
}

// round 8
// speedup vs baseline: 1.3430x; 1.3430x over previous
#include <cuda_runtime.h>
#include <math.h>

#define N_NODES 4096
#define WORDS   64
#define HID     256
#define VOCAB   50257
#define NCLASS  4
#define N_LEAF  2048

// ---------------- device scratch (static: no allocations allowed) ----------------
__device__ float    g_ET[(size_t)VOCAB * HID];   // E transposed: [VOCAB][HID]
__device__ float    g_X [N_NODES * HID];         // gathered embeddings
__device__ float    g_WX[N_NODES * 3 * HID];     // [n][ z | r | h ]
__device__ float    g_UZP[HID * HID];            // packed U_z (eighth-split layout, see k_packU)
__device__ float    g_URP[HID * HID];
__device__ float    g_UHP[HID * HID];
__device__ float    g_H [N_NODES * HID];         // node hidden states
__device__ float    g_PR[N_NODES * HID];         // published ph*r slices (intra-node exchange)
__device__ unsigned g_flag[N_NODES];             // node-done counters (8 = complete)
__device__ unsigned g_exc[N_NODES];              // intra-node exchange counters (8 = complete)
__device__ float    g_red[32 * HID];             // leaf-max partials

// ---------------- helpers ----------------
__device__ __forceinline__ unsigned ld_acq(const unsigned* p) {
    unsigned v;
    asm volatile("ld.acquire.gpu.global.u32 %0, [%1];" : "=r"(v) : "l"(p) : "memory");
    return v;
}
__device__ __forceinline__ void red_add_release(unsigned* p) {
    asm volatile("red.add.release.gpu.global.u32 [%0], %1;" :: "l"(p), "r"(1u) : "memory");
}
__device__ __forceinline__ unsigned long long pk2(float a, float b) {
    unsigned long long r;
    asm("mov.b64 %0, {%1, %2};" : "=l"(r) : "f"(a), "f"(b));
    return r;
}
__device__ __forceinline__ unsigned long long ffma2(unsigned long long a, unsigned long long b,
                                                    unsigned long long c) {
    unsigned long long d;
    asm("fma.rn.f32x2 %0, %1, %2, %3;" : "=l"(d) : "l"(a), "l"(b), "l"(c));
    return d;
}
__device__ __forceinline__ float hsum2(unsigned long long a) {
    float lo, hi;
    asm("mov.b64 {%0, %1}, %2;" : "=f"(lo), "=f"(hi) : "l"(a));
    return lo + hi;
}

// ---------------- kernels ----------------

__global__ void k_zero_flags() {
    int i = blockIdx.x * blockDim.x + threadIdx.x;
    if (i < N_NODES) {
        g_flag[i] = (i == 0) ? 8u : 0u;   // node 0 produced by gather
        g_exc[i] = 0u;
    }
}

// Tiled transpose E (HID, VOCAB) -> g_ET (VOCAB, HID)
__global__ void k_transposeE(const float* __restrict__ E) {
    __shared__ float tile[32][33];
    int v0 = blockIdx.x * 32;
    int h0 = blockIdx.y * 32;
    int x = threadIdx.x, y = threadIdx.y;  // block (32,8)
    #pragma unroll
    for (int j = 0; j < 32; j += 8) {
        int v = v0 + x;
        if (v < VOCAB) tile[y + j][x] = E[(size_t)(h0 + y + j) * VOCAB + v];
    }
    __syncthreads();
    #pragma unroll
    for (int j = 0; j < 32; j += 8) {
        int v = v0 + y + j;
        if (v < VOCAB) g_ET[(size_t)v * HID + h0 + x] = tile[x][y + j];
    }
}

// Pack U for the eighth-split GRU:
// float4 index ((q*8+ks)*8+kq)*32 + o  holds  U[t=q*32+o][k=ks*32+kq*4 .. +3]
__global__ void k_packU(const float* __restrict__ Uz,
                        const float* __restrict__ Ur,
                        const float* __restrict__ Uh) {
    int gid = blockIdx.x * blockDim.x + threadIdx.x;
    if (gid >= 3 * HID * HID) return;
    int m   = gid >> 16;
    int idx = gid & 65535;
    int t = idx >> 8;
    int k = idx & 255;
    int q = t >> 5, o = t & 31;
    int ks = k >> 5, kk = k & 31, kq = kk >> 2, j = kk & 3;
    int dst = (((q * 8 + ks) * 8 + kq) * 32 + o) * 4 + j;
    const float* src = (m == 0) ? Uz : (m == 1) ? Ur : Uh;
    float*       d   = (m == 0) ? g_UZP : (m == 1) ? g_URP : g_UHP;
    d[dst] = src[t * HID + k];
}

// X[n][t] = sum_w ET[tree[n][w]][t];  also seeds h[0] = X[0]
__global__ __launch_bounds__(HID) void k_gather(const int* __restrict__ tree) {
    int n = blockIdx.x;
    int t = threadIdx.x;
    __shared__ int w[WORDS];
    if (t < WORDS) w[t] = tree[n * WORDS + t];
    __syncthreads();
    float acc = 0.f;
    #pragma unroll 8
    for (int i = 0; i < WORDS; i++)
        acc += g_ET[(size_t)w[i] * HID + t];
    g_X[n * HID + t] = acc;
    if (n == 0) g_H[t] = acc;
}

// WX = X @ [Wz;Wr;Wh]^T  : (4096 x 768), K = 256.  64x64 tile, 4x4 micro.
#define GTM 64
#define GTN 64
#define GTK 32
__global__ __launch_bounds__(256) void k_gemm(const float* __restrict__ Wz,
                                              const float* __restrict__ Wr,
                                              const float* __restrict__ Wh) {
    __shared__ float As[GTK][65];
    __shared__ float Bs[GTK][65];
    int mB = blockIdx.x;
    int jB = blockIdx.y;
    int tid = threadIdx.x;
    int tm = tid >> 4;
    int tn = tid & 15;

    int gate = (jB * GTN) >> 8;
    const float* W = (gate == 0) ? Wz : (gate == 1) ? Wr : Wh;
    int jrow0 = jB * GTN - gate * HID;

    int lrow = tid >> 3;
    int lq   = tid & 7;

    float acc[4][4];
    #pragma unroll
    for (int i = 0; i < 4; i++)
        #pragma unroll
        for (int j = 0; j < 4; j++) acc[i][j] = 0.f;

    for (int kt = 0; kt < HID; kt += GTK) {
        #pragma unroll
        for (int p = 0; p < 2; p++) {
            int r = lrow + p * 32;
            float4 a = *reinterpret_cast<const float4*>(&g_X[(mB * GTM + r) * HID + kt + lq * 4]);
            As[lq * 4 + 0][r] = a.x; As[lq * 4 + 1][r] = a.y;
            As[lq * 4 + 2][r] = a.z; As[lq * 4 + 3][r] = a.w;
            float4 b = *reinterpret_cast<const float4*>(&W[(jrow0 + r) * HID + kt + lq * 4]);
            Bs[lq * 4 + 0][r] = b.x; Bs[lq * 4 + 1][r] = b.y;
            Bs[lq * 4 + 2][r] = b.z; Bs[lq * 4 + 3][r] = b.w;
        }
        __syncthreads();
        #pragma unroll
        for (int kk = 0; kk < GTK; kk++) {
            float a0 = As[kk][tm * 4 + 0], a1 = As[kk][tm * 4 + 1];
            float a2 = As[kk][tm * 4 + 2], a3 = As[kk][tm * 4 + 3];
            float b0 = Bs[kk][tn * 4 + 0], b1 = Bs[kk][tn * 4 + 1];
            float b2 = Bs[kk][tn * 4 + 2], b3 = Bs[kk][tn * 4 + 3];
            acc[0][0] = fmaf(a0, b0, acc[0][0]); acc[0][1] = fmaf(a0, b1, acc[0][1]);
            acc[0][2] = fmaf(a0, b2, acc[0][2]); acc[0][3] = fmaf(a0, b3, acc[0][3]);
            acc[1][0] = fmaf(a1, b0, acc[1][0]); acc[1][1] = fmaf(a1, b1, acc[1][1]);
            acc[1][2] = fmaf(a1, b2, acc[1][2]); acc[1][3] = fmaf(a1, b3, acc[1][3]);
            acc[2][0] = fmaf(a2, b0, acc[2][0]); acc[2][1] = fmaf(a2, b1, acc[2][1]);
            acc[2][2] = fmaf(a2, b2, acc[2][2]); acc[2][3] = fmaf(a2, b3, acc[2][3]);
            acc[3][0] = fmaf(a3, b0, acc[3][0]); acc[3][1] = fmaf(a3, b1, acc[3][1]);
            acc[3][2] = fmaf(a3, b2, acc[3][2]); acc[3][3] = fmaf(a3, b3, acc[3][3]);
        }
        __syncthreads();
    }
    #pragma unroll
    for (int i = 0; i < 4; i++) {
        int m = mB * GTM + tm * 4 + i;
        #pragma unroll
        for (int j = 0; j < 4; j++)
            g_WX[m * (3 * HID) + jB * GTN + tn * 4 + j] = acc[i][j];
    }
}

// GRU wavefront, 8 CTAs per node (32 outputs each).
// Parent-independent data prefetched before the spin (U_z,U_r -> registers,
// U_h -> SMEM). Sync fix vs R6: ONLY thread 0 of each CTA polls the global
// flags (8 pollers per line instead of 64 warps), so the producer's
// red.add.release lands at native L2 latency instead of queueing behind a
// polling storm; the result is broadcast CTA-wide with __syncthreads().
__global__ __launch_bounds__(256, 2) void k_gru(const int* __restrict__ edge,
                                                const float* __restrict__ bz,
                                                const float* __restrict__ br,
                                                const float* __restrict__ bh) {
    int grp  = blockIdx.x >> 3;
    int q    = blockIdx.x & 7;
    int node = grp + 1;
    int tid  = threadIdx.x;
    int o    = tid & 31;
    int ks   = tid >> 5;   // 0..7 (K slice)

    __shared__ float  sph[HID];
    __shared__ float  spr[HID];
    __shared__ float  saz[8][32];
    __shared__ float  sar[8][32];
    __shared__ float  sch[8][32];
    __shared__ float  sz[32];
    __shared__ float4 uhs[8 * 256];   // 32KB U_h slice (manual spill)

    const float4* UZ4 = reinterpret_cast<const float4*>(g_UZP);
    const float4* UR4 = reinterpret_cast<const float4*>(g_URP);
    const float4* UH4 = reinterpret_cast<const float4*>(g_UHP);

    int p = edge[node * 2];

    // ---- parent-independent prefetch (off the critical path) ----
    int B = ((q * 8 + ks) * 8) * 32 + o;   // float4 tile base; +kq*32 per k step
    float4 uz[8], ur[8];
    #pragma unroll
    for (int i = 0; i < 8; i++) {
        uz[i] = UZ4[B + i * 32];
        ur[i] = UR4[B + i * 32];
        uhs[i * 256 + tid] = UH4[B + i * 32];
    }

    float wzx = 0.f, wrx = 0.f, whx = 0.f, bzv = 0.f, brv = 0.f, bhv = 0.f;
    if (tid < 32) {
        int t = q * 32 + o;
        wzx = g_WX[node * (3 * HID) + t];
        wrx = g_WX[node * (3 * HID) + HID + t];
        whx = g_WX[node * (3 * HID) + 2 * HID + t];
        bzv = bz[t]; brv = br[t]; bhv = bh[t];
    }

    // ---- wait for parent: single-thread poll, CTA-wide broadcast ----
    if (tid == 0) {
        while (ld_acq(&g_flag[p]) < 8u) { }
    }
    __syncthreads();
    sph[tid] = __ldcg(&g_H[p * HID + tid]);
    __syncthreads();

    // ---- phase 1: z, r partial dots from registers (K slice ks: 32 values) ----
    const unsigned long long* sph64 = reinterpret_cast<const unsigned long long*>(sph);
    unsigned long long az0 = 0ull, az1 = 0ull, ar0 = 0ull, ar1 = 0ull;
    int pb = ks * 16;   // ull base for this K slice
    #pragma unroll
    for (int kq = 0; kq < 8; kq++) {
        unsigned long long p0 = sph64[pb + kq * 2];
        unsigned long long p1 = sph64[pb + kq * 2 + 1];
        az0 = ffma2(pk2(uz[kq].x, uz[kq].y), p0, az0);
        az1 = ffma2(pk2(uz[kq].z, uz[kq].w), p1, az1);
        ar0 = ffma2(pk2(ur[kq].x, ur[kq].y), p0, ar0);
        ar1 = ffma2(pk2(ur[kq].z, ur[kq].w), p1, ar1);
    }
    saz[ks][o] = hsum2(az0) + hsum2(az1);
    sar[ks][o] = hsum2(ar0) + hsum2(ar1);
    __syncthreads();

    if (tid < 32) {
        int t = q * 32 + o;
        float az = wzx + bzv, ar = wrx + brv;
        #pragma unroll
        for (int j = 0; j < 8; j++) { az += saz[j][o]; ar += sar[j][o]; }
        float z = 1.f / (1.f + __expf(-az));
        float r = 1.f / (1.f + __expf(-ar));
        float prv = sph[t] * r;
        sz[o] = z;
        g_PR[node * HID + t] = prv;
        __threadfence();
    }
    __syncthreads();
    if (tid == 0) red_add_release(&g_exc[node]);

    // ---- intra-node exchange: single-thread poll, then gather full pr ----
    if (tid == 0) {
        while (ld_acq(&g_exc[node]) < 8u) { }
    }
    __syncthreads();
    spr[tid] = __ldcg(&g_PR[node * HID + tid]);
    __syncthreads();

    // ---- phase 2: h partial dots with SMEM-prefetched U_h ----
    const unsigned long long* spr64 = reinterpret_cast<const unsigned long long*>(spr);
    unsigned long long ah0 = 0ull, ah1 = 0ull;
    #pragma unroll
    for (int kq = 0; kq < 8; kq++) {
        float4 uh = uhs[kq * 256 + tid];
        unsigned long long p0 = spr64[pb + kq * 2];
        unsigned long long p1 = spr64[pb + kq * 2 + 1];
        ah0 = ffma2(pk2(uh.x, uh.y), p0, ah0);
        ah1 = ffma2(pk2(uh.z, uh.w), p1, ah1);
    }
    sch[ks][o] = hsum2(ah0) + hsum2(ah1);
    __syncthreads();

    if (tid < 32) {
        int t = q * 32 + o;
        float ahv = whx + bhv;
        #pragma unroll
        for (int j = 0; j < 8; j++) ahv += sch[j][o];
        float c = tanhf(ahv);
        float z = sz[o];
        float h = z * sph[t] + (1.f - z) * c;
        g_H[node * HID + t] = h;
        __threadfence();
    }
    __syncthreads();
    if (tid == 0) red_add_release(&g_flag[node]);
}

// 32 partial leaf-max blocks
__global__ __launch_bounds__(HID) void k_leafmax(const int* __restrict__ leaf) {
    int b = blockIdx.x;
    int t = threadIdx.x;
    float m = -INFINITY;
    for (int i = b; i < N_LEAF; i += 32) {
        int n = leaf[i];
        m = fmaxf(m, g_H[n * HID + t]);
    }
    g_red[b * HID + t] = m;
}

__global__ __launch_bounds__(HID) void k_final(const float* __restrict__ Wout,
                                               const float* __restrict__ bout,
                                               const float* __restrict__ y,
                                               float* __restrict__ out, int out_size) {
    __shared__ float f[HID];
    __shared__ float red[HID];
    __shared__ float logits[NCLASS];
    int t = threadIdx.x;
    float m = g_red[t];
    #pragma unroll
    for (int b = 1; b < 32; b++) m = fmaxf(m, g_red[b * HID + t]);
    f[t] = m;
    __syncthreads();
    for (int c = 0; c < NCLASS; c++) {
        red[t] = Wout[c * HID + t] * f[t];
        __syncthreads();
        for (int s = HID / 2; s > 0; s >>= 1) {
            if (t < s) red[t] += red[t + s];
            __syncthreads();
        }
        if (t == 0) logits[c] = red[0] + bout[c];
        __syncthreads();
    }
    if (t == 0) {
        float mx = logits[0];
        for (int c = 1; c < NCLASS; c++) mx = fmaxf(mx, logits[c]);
        float e[NCLASS], s = 0.f;
        for (int c = 0; c < NCLASS; c++) { e[c] = expf(logits[c] - mx); s += e[c]; }
        float loss = 0.f;
        for (int c = 0; c < NCLASS; c++) {
            float pred = e[c] / s;
            float d = y[c] - pred;
            loss += d * d;
            if (c < out_size) out[c] = pred;
        }
        if (out_size > NCLASS) out[NCLASS] = loss;
    }
    for (int i = NCLASS + 1 + t; i < out_size; i += HID) out[i] = 0.f;
}

// ---------------- launch ----------------
extern "C" void kernel_launch(void* const* d_in, const int* in_sizes, int n_in,
                              void* d_out, int out_size) {
    const int*   tree  = (const int*)  d_in[0];
    const int*   edge  = (const int*)  d_in[1];
    const int*   leaf  = (const int*)  d_in[2];
    const float* y     = (const float*)d_in[3];
    const float* E     = (const float*)d_in[4];
    const float* W_z   = (const float*)d_in[5];
    const float* U_z   = (const float*)d_in[6];
    const float* b_z   = (const float*)d_in[7];
    const float* W_r   = (const float*)d_in[8];
    const float* U_r   = (const float*)d_in[9];
    const float* b_r   = (const float*)d_in[10];
    const float* W_h   = (const float*)d_in[11];
    const float* U_h   = (const float*)d_in[12];
    const float* b_h   = (const float*)d_in[13];
    const float* W_out = (const float*)d_in[14];
    const float* b_out = (const float*)d_in[15];
    float* out = (float*)d_out;

    k_zero_flags<<<(N_NODES + 255) / 256, 256>>>();

    dim3 tb(32, 8);
    dim3 tg((VOCAB + 31) / 32, HID / 32);
    k_transposeE<<<tg, tb>>>(E);

    k_packU<<<(3 * HID * HID + 255) / 256, 256>>>(U_z, U_r, U_h);

    k_gather<<<N_NODES, HID>>>(tree);

    dim3 gg(N_NODES / GTM, (3 * HID) / GTN);
    k_gemm<<<gg, 256>>>(W_z, W_r, W_h);

    k_gru<<<8 * (N_NODES - 1), 256>>>(edge, b_z, b_r, b_h);

    k_leafmax<<<32, HID>>>(leaf);
    k_final<<<1, HID>>>(W_out, b_out, y, out, out_size);
}

// round 10
// speedup vs baseline: 1.3776x; 1.0258x over previous
#include <cuda_runtime.h>
#include <math.h>

#define N_NODES 4096
#define WORDS   64
#define HID     256
#define VOCAB   50257
#define NCLASS  4
#define N_LEAF  2048

// ---------------- device scratch (static: no allocations allowed) ----------------
__device__ float    g_ET[(size_t)VOCAB * HID];   // E transposed: [VOCAB][HID]
__device__ float    g_X [N_NODES * HID];         // gathered embeddings
__device__ float    g_WX[N_NODES * 3 * HID];     // [n][ z | r | h ]
__device__ float    g_UZP[HID * HID];            // packed U_z (quarter-split layout, see k_packU)
__device__ float    g_URP[HID * HID];
__device__ float    g_UHP[HID * HID];
__device__ float    g_H [N_NODES * HID];         // node hidden states
__device__ float    g_PR[N_NODES * HID];         // published ph*r quarters (intra-node exchange)
__device__ unsigned g_flag[N_NODES];             // node-done counters (4 = complete)
__device__ unsigned g_exc[N_NODES];              // intra-node exchange counters (4 = complete)
__device__ float    g_red[32 * HID];             // leaf-max partials

// ---------------- helpers ----------------
__device__ __forceinline__ unsigned ld_acq(const unsigned* p) {
    unsigned v;
    asm volatile("ld.acquire.gpu.global.u32 %0, [%1];" : "=r"(v) : "l"(p) : "memory");
    return v;
}
__device__ __forceinline__ void red_add_release(unsigned* p) {
    asm volatile("red.add.release.gpu.global.u32 [%0], %1;" :: "l"(p), "r"(1u) : "memory");
}
__device__ __forceinline__ unsigned long long pk2(float a, float b) {
    unsigned long long r;
    asm("mov.b64 %0, {%1, %2};" : "=l"(r) : "f"(a), "f"(b));
    return r;
}
__device__ __forceinline__ unsigned long long ffma2(unsigned long long a, unsigned long long b,
                                                    unsigned long long c) {
    unsigned long long d;
    asm("fma.rn.f32x2 %0, %1, %2, %3;" : "=l"(d) : "l"(a), "l"(b), "l"(c));
    return d;
}
__device__ __forceinline__ float hsum2(unsigned long long a) {
    float lo, hi;
    asm("mov.b64 {%0, %1}, %2;" : "=f"(lo), "=f"(hi) : "l"(a));
    return lo + hi;
}

// ---------------- kernels ----------------

__global__ void k_zero_flags() {
    int i = blockIdx.x * blockDim.x + threadIdx.x;
    if (i < N_NODES) {
        g_flag[i] = (i == 0) ? 4u : 0u;   // node 0 produced by gather
        g_exc[i] = 0u;
    }
}

// Tiled transpose E (HID, VOCAB) -> g_ET (VOCAB, HID)
__global__ void k_transposeE(const float* __restrict__ E) {
    __shared__ float tile[32][33];
    int v0 = blockIdx.x * 32;
    int h0 = blockIdx.y * 32;
    int x = threadIdx.x, y = threadIdx.y;  // block (32,8)
    #pragma unroll
    for (int j = 0; j < 32; j += 8) {
        int v = v0 + x;
        if (v < VOCAB) tile[y + j][x] = E[(size_t)(h0 + y + j) * VOCAB + v];
    }
    __syncthreads();
    #pragma unroll
    for (int j = 0; j < 32; j += 8) {
        int v = v0 + y + j;
        if (v < VOCAB) g_ET[(size_t)v * HID + h0 + x] = tile[x][y + j];
    }
}

// Pack U for the quarter-split GRU:
// float4 index ((q*4+ks)*16 + kq)*64 + o  holds  U[t=q*64+o][k=ks*64+kq*4 .. +3]
__global__ void k_packU(const float* __restrict__ Uz,
                        const float* __restrict__ Ur,
                        const float* __restrict__ Uh) {
    int gid = blockIdx.x * blockDim.x + threadIdx.x;
    if (gid >= 3 * HID * HID) return;
    int m   = gid >> 16;
    int idx = gid & 65535;
    int t = idx >> 8;
    int k = idx & 255;
    int q = t >> 6, o = t & 63;
    int ks = k >> 6, kk = k & 63, kq = kk >> 2, j = kk & 3;
    int dst = (((q * 4 + ks) * 16 + kq) * 64 + o) * 4 + j;
    const float* src = (m == 0) ? Uz : (m == 1) ? Ur : Uh;
    float*       d   = (m == 0) ? g_UZP : (m == 1) ? g_URP : g_UHP;
    d[dst] = src[t * HID + k];
}

// X[n][t] = sum_w ET[tree[n][w]][t];  also seeds h[0] = X[0]
__global__ __launch_bounds__(HID) void k_gather(const int* __restrict__ tree) {
    int n = blockIdx.x;
    int t = threadIdx.x;
    __shared__ int w[WORDS];
    if (t < WORDS) w[t] = tree[n * WORDS + t];
    __syncthreads();
    float acc = 0.f;
    #pragma unroll 8
    for (int i = 0; i < WORDS; i++)
        acc += g_ET[(size_t)w[i] * HID + t];
    g_X[n * HID + t] = acc;
    if (n == 0) g_H[t] = acc;
}

// WX = X @ [Wz;Wr;Wh]^T  : (4096 x 768), K = 256.  64x64 tile, 4x4 micro.
#define GTM 64
#define GTN 64
#define GTK 32
__global__ __launch_bounds__(256) void k_gemm(const float* __restrict__ Wz,
                                              const float* __restrict__ Wr,
                                              const float* __restrict__ Wh) {
    __shared__ float As[GTK][65];
    __shared__ float Bs[GTK][65];
    int mB = blockIdx.x;
    int jB = blockIdx.y;
    int tid = threadIdx.x;
    int tm = tid >> 4;
    int tn = tid & 15;

    int gate = (jB * GTN) >> 8;
    const float* W = (gate == 0) ? Wz : (gate == 1) ? Wr : Wh;
    int jrow0 = jB * GTN - gate * HID;

    int lrow = tid >> 3;
    int lq   = tid & 7;

    float acc[4][4];
    #pragma unroll
    for (int i = 0; i < 4; i++)
        #pragma unroll
        for (int j = 0; j < 4; j++) acc[i][j] = 0.f;

    for (int kt = 0; kt < HID; kt += GTK) {
        #pragma unroll
        for (int p = 0; p < 2; p++) {
            int r = lrow + p * 32;
            float4 a = *reinterpret_cast<const float4*>(&g_X[(mB * GTM + r) * HID + kt + lq * 4]);
            As[lq * 4 + 0][r] = a.x; As[lq * 4 + 1][r] = a.y;
            As[lq * 4 + 2][r] = a.z; As[lq * 4 + 3][r] = a.w;
            float4 b = *reinterpret_cast<const float4*>(&W[(jrow0 + r) * HID + kt + lq * 4]);
            Bs[lq * 4 + 0][r] = b.x; Bs[lq * 4 + 1][r] = b.y;
            Bs[lq * 4 + 2][r] = b.z; Bs[lq * 4 + 3][r] = b.w;
        }
        __syncthreads();
        #pragma unroll
        for (int kk = 0; kk < GTK; kk++) {
            float a0 = As[kk][tm * 4 + 0], a1 = As[kk][tm * 4 + 1];
            float a2 = As[kk][tm * 4 + 2], a3 = As[kk][tm * 4 + 3];
            float b0 = Bs[kk][tn * 4 + 0], b1 = Bs[kk][tn * 4 + 1];
            float b2 = Bs[kk][tn * 4 + 2], b3 = Bs[kk][tn * 4 + 3];
            acc[0][0] = fmaf(a0, b0, acc[0][0]); acc[0][1] = fmaf(a0, b1, acc[0][1]);
            acc[0][2] = fmaf(a0, b2, acc[0][2]); acc[0][3] = fmaf(a0, b3, acc[0][3]);
            acc[1][0] = fmaf(a1, b0, acc[1][0]); acc[1][1] = fmaf(a1, b1, acc[1][1]);
            acc[1][2] = fmaf(a1, b2, acc[1][2]); acc[1][3] = fmaf(a1, b3, acc[1][3]);
            acc[2][0] = fmaf(a2, b0, acc[2][0]); acc[2][1] = fmaf(a2, b1, acc[2][1]);
            acc[2][2] = fmaf(a2, b2, acc[2][2]); acc[2][3] = fmaf(a2, b3, acc[2][3]);
            acc[3][0] = fmaf(a3, b0, acc[3][0]); acc[3][1] = fmaf(a3, b1, acc[3][1]);
            acc[3][2] = fmaf(a3, b2, acc[3][2]); acc[3][3] = fmaf(a3, b3, acc[3][3]);
        }
        __syncthreads();
    }
    #pragma unroll
    for (int i = 0; i < 4; i++) {
        int m = mB * GTM + tm * 4 + i;
        #pragma unroll
        for (int j = 0; j < 4; j++)
            g_WX[m * (3 * HID) + jB * GTN + tn * 4 + j] = acc[i][j];
    }
}

// GRU wavefront, 4 CTAs per node (64 outputs each), serial-path-minimized:
//  - U_r and U_h slices live in REGISTERS (prefetched before the parent spin)
//  - U_z (z gate) is consumed only at the final combine, so it is streamed
//    from L2/L1 DURING the pr-exchange gap: zero serial cost
//  - single-thread flag polls broadcast via __syncthreads (R7 fix)
//  - 4-arrival RED chains (vs 8 in R7)
__global__ __launch_bounds__(256, 1) void k_gru(const int* __restrict__ edge,
                                                const float* __restrict__ bz,
                                                const float* __restrict__ br,
                                                const float* __restrict__ bh) {
    int grp  = blockIdx.x >> 2;
    int q    = blockIdx.x & 3;
    int node = grp + 1;
    int tid  = threadIdx.x;
    int o    = tid & 63;
    int ks   = tid >> 6;   // 0..3 (K slice of 64)

    __shared__ float sph[HID];
    __shared__ float spr[HID];
    __shared__ float saz[4][64];
    __shared__ float sar[4][64];
    __shared__ float sch[4][64];

    const float4* UZ4 = reinterpret_cast<const float4*>(g_UZP);
    const float4* UR4 = reinterpret_cast<const float4*>(g_URP);
    const float4* UH4 = reinterpret_cast<const float4*>(g_UHP);

    int p = edge[node * 2];

    // ---- parent-independent prefetch: U_r, U_h slices into registers ----
    int B = ((q * 4 + ks) * 16) * 64 + o;   // float4 tile base; +kq*64 per k step
    float4 ur[16], uh[16];
    #pragma unroll
    for (int i = 0; i < 16; i++) {
        ur[i] = UR4[B + i * 64];
        uh[i] = UH4[B + i * 64];
    }

    float wzx = 0.f, wrx = 0.f, whx = 0.f, bzv = 0.f, brv = 0.f, bhv = 0.f;
    if (tid < 64) {
        int t = q * 64 + o;
        wzx = g_WX[node * (3 * HID) + t];
        wrx = g_WX[node * (3 * HID) + HID + t];
        whx = g_WX[node * (3 * HID) + 2 * HID + t];
        bzv = bz[t]; brv = br[t]; bhv = bh[t];
    }

    // ---- wait for parent: single-thread poll, CTA-wide broadcast ----
    if (tid == 0) {
        while (ld_acq(&g_flag[p]) < 4u) { }
    }
    __syncthreads();
    if (tid < 64) {
        float4 v;
        v.x = __ldcg(&g_H[p * HID + tid * 4 + 0]);
        v.y = __ldcg(&g_H[p * HID + tid * 4 + 1]);
        v.z = __ldcg(&g_H[p * HID + tid * 4 + 2]);
        v.w = __ldcg(&g_H[p * HID + tid * 4 + 3]);
        reinterpret_cast<float4*>(sph)[tid] = v;
    }
    __syncthreads();

    // ---- r-gate partial dots from registers (K slice ks: 64 values) ----
    const unsigned long long* sph64 = reinterpret_cast<const unsigned long long*>(sph);
    unsigned long long ar0 = 0ull, ar1 = 0ull;
    int pb = ks * 32;   // ull base for this K slice
    #pragma unroll
    for (int kq = 0; kq < 16; kq++) {
        unsigned long long p0 = sph64[pb + kq * 2];
        unsigned long long p1 = sph64[pb + kq * 2 + 1];
        ar0 = ffma2(pk2(ur[kq].x, ur[kq].y), p0, ar0);
        ar1 = ffma2(pk2(ur[kq].z, ur[kq].w), p1, ar1);
    }
    sar[ks][o] = hsum2(ar0) + hsum2(ar1);
    __syncthreads();

    if (tid < 64) {
        int t = q * 64 + o;
        float ar = wrx + brv + sar[0][o] + sar[1][o] + sar[2][o] + sar[3][o];
        float r = 1.f / (1.f + __expf(-ar));
        float prv = sph[t] * r;
        g_PR[node * HID + t] = prv;
        __threadfence();
    }
    __syncthreads();
    if (tid == 0) red_add_release(&g_exc[node]);

    // ---- GAP WORK: z-gate partial dots, streaming U_z from L2/L1.
    //      z is only needed at the final combine, so this latency hides
    //      under sibling publish skew + exchange detect. ----
    unsigned long long az0 = 0ull, az1 = 0ull;
    #pragma unroll
    for (int kq = 0; kq < 16; kq++) {
        float4 uz = __ldg(&UZ4[B + kq * 64]);
        unsigned long long p0 = sph64[pb + kq * 2];
        unsigned long long p1 = sph64[pb + kq * 2 + 1];
        az0 = ffma2(pk2(uz.x, uz.y), p0, az0);
        az1 = ffma2(pk2(uz.z, uz.w), p1, az1);
    }
    saz[ks][o] = hsum2(az0) + hsum2(az1);

    // ---- intra-node exchange: single-thread poll, then gather full pr ----
    if (tid == 0) {
        while (ld_acq(&g_exc[node]) < 4u) { }
    }
    __syncthreads();
    if (tid < 64) {
        float4 v;
        v.x = __ldcg(&g_PR[node * HID + tid * 4 + 0]);
        v.y = __ldcg(&g_PR[node * HID + tid * 4 + 1]);
        v.z = __ldcg(&g_PR[node * HID + tid * 4 + 2]);
        v.w = __ldcg(&g_PR[node * HID + tid * 4 + 3]);
        reinterpret_cast<float4*>(spr)[tid] = v;
    }
    __syncthreads();

    // ---- h-candidate partial dots with register-resident U_h ----
    const unsigned long long* spr64 = reinterpret_cast<const unsigned long long*>(spr);
    unsigned long long ah0 = 0ull, ah1 = 0ull;
    #pragma unroll
    for (int kq = 0; kq < 16; kq++) {
        unsigned long long p0 = spr64[pb + kq * 2];
        unsigned long long p1 = spr64[pb + kq * 2 + 1];
        ah0 = ffma2(pk2(uh[kq].x, uh[kq].y), p0, ah0);
        ah1 = ffma2(pk2(uh[kq].z, uh[kq].w), p1, ah1);
    }
    sch[ks][o] = hsum2(ah0) + hsum2(ah1);
    __syncthreads();

    if (tid < 64) {
        int t = q * 64 + o;
        float az = wzx + bzv + saz[0][o] + saz[1][o] + saz[2][o] + saz[3][o];
        float z = 1.f / (1.f + __expf(-az));
        float ahv = whx + bhv + sch[0][o] + sch[1][o] + sch[2][o] + sch[3][o];
        float c = tanhf(ahv);
        float h = z * sph[t] + (1.f - z) * c;
        g_H[node * HID + t] = h;
        __threadfence();
    }
    __syncthreads();
    if (tid == 0) red_add_release(&g_flag[node]);
}

// 32 partial leaf-max blocks
__global__ __launch_bounds__(HID) void k_leafmax(const int* __restrict__ leaf) {
    int b = blockIdx.x;
    int t = threadIdx.x;
    float m = -INFINITY;
    for (int i = b; i < N_LEAF; i += 32) {
        int n = leaf[i];
        m = fmaxf(m, g_H[n * HID + t]);
    }
    g_red[b * HID + t] = m;
}

__global__ __launch_bounds__(HID) void k_final(const float* __restrict__ Wout,
                                               const float* __restrict__ bout,
                                               const float* __restrict__ y,
                                               float* __restrict__ out, int out_size) {
    __shared__ float f[HID];
    __shared__ float red[HID];
    __shared__ float logits[NCLASS];
    int t = threadIdx.x;
    float m = g_red[t];
    #pragma unroll
    for (int b = 1; b < 32; b++) m = fmaxf(m, g_red[b * HID + t]);
    f[t] = m;
    __syncthreads();
    for (int c = 0; c < NCLASS; c++) {
        red[t] = Wout[c * HID + t] * f[t];
        __syncthreads();
        for (int s = HID / 2; s > 0; s >>= 1) {
            if (t < s) red[t] += red[t + s];
            __syncthreads();
        }
        if (t == 0) logits[c] = red[0] + bout[c];
        __syncthreads();
    }
    if (t == 0) {
        float mx = logits[0];
        for (int c = 1; c < NCLASS; c++) mx = fmaxf(mx, logits[c]);
        float e[NCLASS], s = 0.f;
        for (int c = 0; c < NCLASS; c++) { e[c] = expf(logits[c] - mx); s += e[c]; }
        float loss = 0.f;
        for (int c = 0; c < NCLASS; c++) {
            float pred = e[c] / s;
            float d = y[c] - pred;
            loss += d * d;
            if (c < out_size) out[c] = pred;
        }
        if (out_size > NCLASS) out[NCLASS] = loss;
    }
    for (int i = NCLASS + 1 + t; i < out_size; i += HID) out[i] = 0.f;
}

// ---------------- launch ----------------
extern "C" void kernel_launch(void* const* d_in, const int* in_sizes, int n_in,
                              void* d_out, int out_size) {
    const int*   tree  = (const int*)  d_in[0];
    const int*   edge  = (const int*)  d_in[1];
    const int*   leaf  = (const int*)  d_in[2];
    const float* y     = (const float*)d_in[3];
    const float* E     = (const float*)d_in[4];
    const float* W_z   = (const float*)d_in[5];
    const float* U_z   = (const float*)d_in[6];
    const float* b_z   = (const float*)d_in[7];
    const float* W_r   = (const float*)d_in[8];
    const float* U_r   = (const float*)d_in[9];
    const float* b_r   = (const float*)d_in[10];
    const float* W_h   = (const float*)d_in[11];
    const float* U_h   = (const float*)d_in[12];
    const float* b_h   = (const float*)d_in[13];
    const float* W_out = (const float*)d_in[14];
    const float* b_out = (const float*)d_in[15];
    float* out = (float*)d_out;

    k_zero_flags<<<(N_NODES + 255) / 256, 256>>>();

    dim3 tb(32, 8);
    dim3 tg((VOCAB + 31) / 32, HID / 32);
    k_transposeE<<<tg, tb>>>(E);

    k_packU<<<(3 * HID * HID + 255) / 256, 256>>>(U_z, U_r, U_h);

    k_gather<<<N_NODES, HID>>>(tree);

    dim3 gg(N_NODES / GTM, (3 * HID) / GTN);
    k_gemm<<<gg, 256>>>(W_z, W_r, W_h);

    k_gru<<<4 * (N_NODES - 1), 256>>>(edge, b_z, b_r, b_h);

    k_leafmax<<<32, HID>>>(leaf);
    k_final<<<1, HID>>>(W_out, b_out, y, out, out_size);
}

// round 12
// speedup vs baseline: 1.7355x; 1.2598x over previous
#include <cuda_runtime.h>
#include <math.h>

#define N_NODES 4096
#define WORDS   64
#define HID     256
#define VOCAB   50257
#define NCLASS  4
#define N_LEAF  2048

// ---------------- device scratch (static: no allocations allowed) ----------------
__device__ float    g_ET[(size_t)VOCAB * HID];   // E transposed: [VOCAB][HID]
__device__ float    g_X [N_NODES * HID];         // gathered embeddings
__device__ float    g_WX[N_NODES * 3 * HID];     // [n][ z | r | h ]
__device__ float    g_UZP[HID * HID];            // packed U_z (quarter-split layout, see k_packU)
__device__ float    g_URP[HID * HID];
__device__ float    g_UHP[HID * HID];
__device__ float    g_H [N_NODES * HID];         // node hidden states
__device__ float    g_PR[N_NODES * HID];         // published ph*r quarters (intra-node exchange)
__device__ unsigned g_flag[N_NODES];             // node-done counters (4 = complete)
__device__ unsigned g_exc[N_NODES];              // intra-node exchange counters (4 = complete)
__device__ float    g_red[32 * HID];             // leaf-max partials

// ---------------- helpers ----------------
__device__ __forceinline__ unsigned ld_acq(const unsigned* p) {
    unsigned v;
    asm volatile("ld.acquire.gpu.global.u32 %0, [%1];" : "=r"(v) : "l"(p) : "memory");
    return v;
}
__device__ __forceinline__ void red_add_release(unsigned* p) {
    asm volatile("red.add.release.gpu.global.u32 [%0], %1;" :: "l"(p), "r"(1u) : "memory");
}
__device__ __forceinline__ unsigned long long pk2(float a, float b) {
    unsigned long long r;
    asm("mov.b64 %0, {%1, %2};" : "=l"(r) : "f"(a), "f"(b));
    return r;
}
__device__ __forceinline__ unsigned long long ffma2(unsigned long long a, unsigned long long b,
                                                    unsigned long long c) {
    unsigned long long d;
    asm("fma.rn.f32x2 %0, %1, %2, %3;" : "=l"(d) : "l"(a), "l"(b), "l"(c));
    return d;
}
__device__ __forceinline__ float hsum2(unsigned long long a) {
    float lo, hi;
    asm("mov.b64 {%0, %1}, %2;" : "=f"(lo), "=f"(hi) : "l"(a));
    return lo + hi;
}

// ---------------- kernels ----------------

__global__ void k_zero_flags() {
    int i = blockIdx.x * blockDim.x + threadIdx.x;
    if (i < N_NODES) {
        g_flag[i] = (i == 0) ? 4u : 0u;   // node 0 produced by gather
        g_exc[i] = 0u;
    }
}

// Tiled transpose E (HID, VOCAB) -> g_ET (VOCAB, HID)
__global__ void k_transposeE(const float* __restrict__ E) {
    __shared__ float tile[32][33];
    int v0 = blockIdx.x * 32;
    int h0 = blockIdx.y * 32;
    int x = threadIdx.x, y = threadIdx.y;  // block (32,8)
    #pragma unroll
    for (int j = 0; j < 32; j += 8) {
        int v = v0 + x;
        if (v < VOCAB) tile[y + j][x] = E[(size_t)(h0 + y + j) * VOCAB + v];
    }
    __syncthreads();
    #pragma unroll
    for (int j = 0; j < 32; j += 8) {
        int v = v0 + y + j;
        if (v < VOCAB) g_ET[(size_t)v * HID + h0 + x] = tile[x][y + j];
    }
}

// Pack U for the quarter-split GRU:
// float4 index ((q*4+ks)*16 + kq)*64 + o  holds  U[t=q*64+o][k=ks*64+kq*4 .. +3]
__global__ void k_packU(const float* __restrict__ Uz,
                        const float* __restrict__ Ur,
                        const float* __restrict__ Uh) {
    int gid = blockIdx.x * blockDim.x + threadIdx.x;
    if (gid >= 3 * HID * HID) return;
    int m   = gid >> 16;
    int idx = gid & 65535;
    int t = idx >> 8;
    int k = idx & 255;
    int q = t >> 6, o = t & 63;
    int ks = k >> 6, kk = k & 63, kq = kk >> 2, j = kk & 3;
    int dst = (((q * 4 + ks) * 16 + kq) * 64 + o) * 4 + j;
    const float* src = (m == 0) ? Uz : (m == 1) ? Ur : Uh;
    float*       d   = (m == 0) ? g_UZP : (m == 1) ? g_URP : g_UHP;
    d[dst] = src[t * HID + k];
}

// X[n][t] = sum_w ET[tree[n][w]][t];  also seeds h[0] = X[0]
__global__ __launch_bounds__(HID) void k_gather(const int* __restrict__ tree) {
    int n = blockIdx.x;
    int t = threadIdx.x;
    __shared__ int w[WORDS];
    if (t < WORDS) w[t] = tree[n * WORDS + t];
    __syncthreads();
    float acc = 0.f;
    #pragma unroll 8
    for (int i = 0; i < WORDS; i++)
        acc += g_ET[(size_t)w[i] * HID + t];
    g_X[n * HID + t] = acc;
    if (n == 0) g_H[t] = acc;
}

// WX = X @ [Wz;Wr;Wh]^T  : (4096 x 768), K = 256.  64x64 tile, 4x4 micro.
#define GTM 64
#define GTN 64
#define GTK 32
__global__ __launch_bounds__(256) void k_gemm(const float* __restrict__ Wz,
                                              const float* __restrict__ Wr,
                                              const float* __restrict__ Wh) {
    __shared__ float As[GTK][65];
    __shared__ float Bs[GTK][65];
    int mB = blockIdx.x;
    int jB = blockIdx.y;
    int tid = threadIdx.x;
    int tm = tid >> 4;
    int tn = tid & 15;

    int gate = (jB * GTN) >> 8;
    const float* W = (gate == 0) ? Wz : (gate == 1) ? Wr : Wh;
    int jrow0 = jB * GTN - gate * HID;

    int lrow = tid >> 3;
    int lq   = tid & 7;

    float acc[4][4];
    #pragma unroll
    for (int i = 0; i < 4; i++)
        #pragma unroll
        for (int j = 0; j < 4; j++) acc[i][j] = 0.f;

    for (int kt = 0; kt < HID; kt += GTK) {
        #pragma unroll
        for (int p = 0; p < 2; p++) {
            int r = lrow + p * 32;
            float4 a = *reinterpret_cast<const float4*>(&g_X[(mB * GTM + r) * HID + kt + lq * 4]);
            As[lq * 4 + 0][r] = a.x; As[lq * 4 + 1][r] = a.y;
            As[lq * 4 + 2][r] = a.z; As[lq * 4 + 3][r] = a.w;
            float4 b = *reinterpret_cast<const float4*>(&W[(jrow0 + r) * HID + kt + lq * 4]);
            Bs[lq * 4 + 0][r] = b.x; Bs[lq * 4 + 1][r] = b.y;
            Bs[lq * 4 + 2][r] = b.z; Bs[lq * 4 + 3][r] = b.w;
        }
        __syncthreads();
        #pragma unroll
        for (int kk = 0; kk < GTK; kk++) {
            float a0 = As[kk][tm * 4 + 0], a1 = As[kk][tm * 4 + 1];
            float a2 = As[kk][tm * 4 + 2], a3 = As[kk][tm * 4 + 3];
            float b0 = Bs[kk][tn * 4 + 0], b1 = Bs[kk][tn * 4 + 1];
            float b2 = Bs[kk][tn * 4 + 2], b3 = Bs[kk][tn * 4 + 3];
            acc[0][0] = fmaf(a0, b0, acc[0][0]); acc[0][1] = fmaf(a0, b1, acc[0][1]);
            acc[0][2] = fmaf(a0, b2, acc[0][2]); acc[0][3] = fmaf(a0, b3, acc[0][3]);
            acc[1][0] = fmaf(a1, b0, acc[1][0]); acc[1][1] = fmaf(a1, b1, acc[1][1]);
            acc[1][2] = fmaf(a1, b2, acc[1][2]); acc[1][3] = fmaf(a1, b3, acc[1][3]);
            acc[2][0] = fmaf(a2, b0, acc[2][0]); acc[2][1] = fmaf(a2, b1, acc[2][1]);
            acc[2][2] = fmaf(a2, b2, acc[2][2]); acc[2][3] = fmaf(a2, b3, acc[2][3]);
            acc[3][0] = fmaf(a3, b0, acc[3][0]); acc[3][1] = fmaf(a3, b1, acc[3][1]);
            acc[3][2] = fmaf(a3, b2, acc[3][2]); acc[3][3] = fmaf(a3, b3, acc[3][3]);
        }
        __syncthreads();
    }
    #pragma unroll
    for (int i = 0; i < 4; i++) {
        int m = mB * GTM + tm * 4 + i;
        #pragma unroll
        for (int j = 0; j < 4; j++)
            g_WX[m * (3 * HID) + jB * GTN + tn * 4 + j] = acc[i][j];
    }
}

// GRU wavefront, 4 CTAs per node (64 outputs each) — R5 champion structure
// with the proven R7 sync fix:
//  - phase 1 streams U_z + U_r from L1/L2 (hot, 192KB working set fits L1)
//  - U_h slice prefetched into registers before the parent spin
//  - ONLY thread 0 polls the parent flag and the exchange counter
//    (poll storm off the L2 line), result broadcast via __syncthreads
//  - ph / pr pickups are 64 x LDG.128 (vectorized)
__global__ __launch_bounds__(256, 2) void k_gru(const int* __restrict__ edge,
                                                const float* __restrict__ bz,
                                                const float* __restrict__ br,
                                                const float* __restrict__ bh) {
    int grp  = blockIdx.x >> 2;
    int q    = blockIdx.x & 3;
    int node = grp + 1;
    int tid  = threadIdx.x;
    int o    = tid & 63;
    int ks   = tid >> 6;   // 0..3 (K slice of 64)

    __shared__ float sph[HID];
    __shared__ float spr[HID];
    __shared__ float saz[4][64];
    __shared__ float sar[4][64];
    __shared__ float sch[4][64];
    __shared__ float sz[64];

    const float4* UZ4 = reinterpret_cast<const float4*>(g_UZP);
    const float4* UR4 = reinterpret_cast<const float4*>(g_URP);
    const float4* UH4 = reinterpret_cast<const float4*>(g_UHP);

    int p = edge[node * 2];

    // ---- parent-independent prefetch: U_h slice into registers ----
    int B = ((q * 4 + ks) * 16) * 64 + o;   // float4 tile base; +kq*64 per k step
    float4 uh[16];
    #pragma unroll
    for (int i = 0; i < 16; i++) uh[i] = UH4[B + i * 64];

    float wzx = 0.f, wrx = 0.f, whx = 0.f, bzv = 0.f, brv = 0.f, bhv = 0.f;
    if (tid < 64) {
        int t = q * 64 + o;
        wzx = g_WX[node * (3 * HID) + t];
        wrx = g_WX[node * (3 * HID) + HID + t];
        whx = g_WX[node * (3 * HID) + 2 * HID + t];
        bzv = bz[t]; brv = br[t]; bhv = bh[t];
    }

    // ---- wait for parent: single-thread poll, CTA-wide broadcast ----
    if (tid == 0) {
        while (ld_acq(&g_flag[p]) < 4u) { }
    }
    __syncthreads();
    if (tid < 64) {
        const float4* ph4 = reinterpret_cast<const float4*>(&g_H[p * HID]);
        reinterpret_cast<float4*>(sph)[tid] = __ldcg(&ph4[tid]);
    }
    __syncthreads();

    // ---- phase 1: z, r partial dots, streaming U_z / U_r (L1-hot) ----
    const unsigned long long* sph64 = reinterpret_cast<const unsigned long long*>(sph);
    unsigned long long az0 = 0ull, az1 = 0ull, ar0 = 0ull, ar1 = 0ull;
    int pb = ks * 32;   // ull base for this K slice
    #pragma unroll 8
    for (int kq = 0; kq < 16; kq++) {
        float4 uz = UZ4[B + kq * 64];
        float4 ur = UR4[B + kq * 64];
        unsigned long long p0 = sph64[pb + kq * 2];
        unsigned long long p1 = sph64[pb + kq * 2 + 1];
        az0 = ffma2(pk2(uz.x, uz.y), p0, az0);
        az1 = ffma2(pk2(uz.z, uz.w), p1, az1);
        ar0 = ffma2(pk2(ur.x, ur.y), p0, ar0);
        ar1 = ffma2(pk2(ur.z, ur.w), p1, ar1);
    }
    saz[ks][o] = hsum2(az0) + hsum2(az1);
    sar[ks][o] = hsum2(ar0) + hsum2(ar1);
    __syncthreads();

    if (tid < 64) {
        int t = q * 64 + o;
        float az = wzx + bzv + saz[0][o] + saz[1][o] + saz[2][o] + saz[3][o];
        float ar = wrx + brv + sar[0][o] + sar[1][o] + sar[2][o] + sar[3][o];
        float z = 1.f / (1.f + __expf(-az));
        float r = 1.f / (1.f + __expf(-ar));
        float prv = sph[t] * r;
        sz[o] = z;
        g_PR[node * HID + t] = prv;
        __threadfence();
    }
    __syncthreads();
    if (tid == 0) red_add_release(&g_exc[node]);

    // ---- intra-node exchange: single-thread poll, then vectorized gather ----
    if (tid == 0) {
        while (ld_acq(&g_exc[node]) < 4u) { }
    }
    __syncthreads();
    if (tid < 64) {
        const float4* pr4 = reinterpret_cast<const float4*>(&g_PR[node * HID]);
        reinterpret_cast<float4*>(spr)[tid] = __ldcg(&pr4[tid]);
    }
    __syncthreads();

    // ---- phase 2: h partial dots with register-resident U_h ----
    const unsigned long long* spr64 = reinterpret_cast<const unsigned long long*>(spr);
    unsigned long long ah0 = 0ull, ah1 = 0ull;
    #pragma unroll
    for (int kq = 0; kq < 16; kq++) {
        unsigned long long p0 = spr64[pb + kq * 2];
        unsigned long long p1 = spr64[pb + kq * 2 + 1];
        ah0 = ffma2(pk2(uh[kq].x, uh[kq].y), p0, ah0);
        ah1 = ffma2(pk2(uh[kq].z, uh[kq].w), p1, ah1);
    }
    sch[ks][o] = hsum2(ah0) + hsum2(ah1);
    __syncthreads();

    if (tid < 64) {
        int t = q * 64 + o;
        float ahv = whx + bhv + sch[0][o] + sch[1][o] + sch[2][o] + sch[3][o];
        float c = tanhf(ahv);
        float z = sz[o];
        float h = z * sph[t] + (1.f - z) * c;
        g_H[node * HID + t] = h;
        __threadfence();
    }
    __syncthreads();
    if (tid == 0) red_add_release(&g_flag[node]);
}

// 32 partial leaf-max blocks
__global__ __launch_bounds__(HID) void k_leafmax(const int* __restrict__ leaf) {
    int b = blockIdx.x;
    int t = threadIdx.x;
    float m = -INFINITY;
    for (int i = b; i < N_LEAF; i += 32) {
        int n = leaf[i];
        m = fmaxf(m, g_H[n * HID + t]);
    }
    g_red[b * HID + t] = m;
}

__global__ __launch_bounds__(HID) void k_final(const float* __restrict__ Wout,
                                               const float* __restrict__ bout,
                                               const float* __restrict__ y,
                                               float* __restrict__ out, int out_size) {
    __shared__ float f[HID];
    __shared__ float red[HID];
    __shared__ float logits[NCLASS];
    int t = threadIdx.x;
    float m = g_red[t];
    #pragma unroll
    for (int b = 1; b < 32; b++) m = fmaxf(m, g_red[b * HID + t]);
    f[t] = m;
    __syncthreads();
    for (int c = 0; c < NCLASS; c++) {
        red[t] = Wout[c * HID + t] * f[t];
        __syncthreads();
        for (int s = HID / 2; s > 0; s >>= 1) {
            if (t < s) red[t] += red[t + s];
            __syncthreads();
        }
        if (t == 0) logits[c] = red[0] + bout[c];
        __syncthreads();
    }
    if (t == 0) {
        float mx = logits[0];
        for (int c = 1; c < NCLASS; c++) mx = fmaxf(mx, logits[c]);
        float e[NCLASS], s = 0.f;
        for (int c = 0; c < NCLASS; c++) { e[c] = expf(logits[c] - mx); s += e[c]; }
        float loss = 0.f;
        for (int c = 0; c < NCLASS; c++) {
            float pred = e[c] / s;
            float d = y[c] - pred;
            loss += d * d;
            if (c < out_size) out[c] = pred;
        }
        if (out_size > NCLASS) out[NCLASS] = loss;
    }
    for (int i = NCLASS + 1 + t; i < out_size; i += HID) out[i] = 0.f;
}

// ---------------- launch ----------------
extern "C" void kernel_launch(void* const* d_in, const int* in_sizes, int n_in,
                              void* d_out, int out_size) {
    const int*   tree  = (const int*)  d_in[0];
    const int*   edge  = (const int*)  d_in[1];
    const int*   leaf  = (const int*)  d_in[2];
    const float* y     = (const float*)d_in[3];
    const float* E     = (const float*)d_in[4];
    const float* W_z   = (const float*)d_in[5];
    const float* U_z   = (const float*)d_in[6];
    const float* b_z   = (const float*)d_in[7];
    const float* W_r   = (const float*)d_in[8];
    const float* U_r   = (const float*)d_in[9];
    const float* b_r   = (const float*)d_in[10];
    const float* W_h   = (const float*)d_in[11];
    const float* U_h   = (const float*)d_in[12];
    const float* b_h   = (const float*)d_in[13];
    const float* W_out = (const float*)d_in[14];
    const float* b_out = (const float*)d_in[15];
    float* out = (float*)d_out;

    k_zero_flags<<<(N_NODES + 255) / 256, 256>>>();

    dim3 tb(32, 8);
    dim3 tg((VOCAB + 31) / 32, HID / 32);
    k_transposeE<<<tg, tb>>>(E);

    k_packU<<<(3 * HID * HID + 255) / 256, 256>>>(U_z, U_r, U_h);

    k_gather<<<N_NODES, HID>>>(tree);

    dim3 gg(N_NODES / GTM, (3 * HID) / GTN);
    k_gemm<<<gg, 256>>>(W_z, W_r, W_h);

    k_gru<<<4 * (N_NODES - 1), 256>>>(edge, b_z, b_r, b_h);

    k_leafmax<<<32, HID>>>(leaf);
    k_final<<<1, HID>>>(W_out, b_out, y, out, out_size);
}